// round 5
// baseline (speedup 1.0000x reference)
#include <cuda_runtime.h>
#include <mma.h>
#include <cstdint>

using namespace nvcuda;

// ---------------------------------------------------------------------------
// PAM via wmma tf32 with 2-term split (3-MMA fp32 emulation, ~21 mantissa bits)
//   WT transposes -> q,k GEMM (N=64) -> v GEMM (transposed store)
//   -> S = q k^T per batch -> row softmax -> out = gamma*(P v) + x
// ---------------------------------------------------------------------------

#define B_    4
#define NTOK  4096
#define CC    512
#define CRD   64
#define BNTOT (B_ * NTOK)

// device scratch (no cudaMalloc allowed)
__device__ float g_q[BNTOT * CRD];
__device__ float g_k[BNTOT * CRD];
__device__ float g_vT[(size_t)B_ * CC * NTOK];   // [b][c][tok]
__device__ float g_S[(size_t)B_ * NTOK * NTOK];  // [b][n][m]
__device__ float g_WbT[CRD * CC];
__device__ float g_WcT[CRD * CC];
__device__ float g_WdT[CC * CC];

__device__ __forceinline__ float f2tf(float f) {
    uint32_t u;
    asm("cvt.rna.tf32.f32 %0, %1;" : "=r"(u) : "f"(f));
    return __uint_as_float(u);
}

// ---------------- tiny W transpose ------------------------------------------
__global__ void transpose_w(const float* __restrict__ W, float* __restrict__ WT,
                            int K, int N) {
    int i = blockIdx.x * 256 + threadIdx.x;
    if (i < K * N) {
        int n = i / K, k = i - n * K;
        WT[i] = W[(size_t)k * N + n];
    }
}

// ---------------- wmma tf32 split GEMM --------------------------------------
// D tile: 128 x TN. A: rows K-major [M,K] (ldA). B: rows K-major [Ntot,K] (ldB).
// 256 threads, 8 warps as 2(m) x 4(n); warp tile 64 x (TN/4).
// K-chunk 32, single smem stage (hi+lo), register-staged prefetch.
// acc += Ahi*Bhi + Ahi*Blo + Alo*Bhi   (fp32 accumulate)
// EPI 0: C[bz*sC + m*ldC + n] = acc
// EPI 1: transposed store (vT): C[(bglob*CC + nglob)*NTOK + tok]
// EPI 2: C = gamma*acc + x
template <int TN, int EPI>
__global__ __launch_bounds__(256) void gemm_wmma(
    const float* __restrict__ A, const float* __restrict__ B,
    float* __restrict__ C, int K, int ldA, int ldB, int ldC, size_t sA,
    size_t sB, size_t sC, const float* __restrict__ xres,
    const float* __restrict__ gamma) {
    extern __shared__ float sm[];
    constexpr int ASZ = 128 * 36;  // floats per A component (hi or lo)
    constexpr int BSZ = TN * 36;
    constexpr int NT = TN / 64;    // 16-wide wmma n-tiles per warp
    constexpr int NB = TN / 32;    // B float4 loads per thread

    float* AsH = sm;
    float* AsL = AsH + ASZ;
    float* BsH = AsL + ASZ;
    float* BsL = BsH + BSZ;

    const int t = threadIdx.x;
    const int wid = t >> 5;
    const int warp_m = wid >> 2;  // 0..1
    const int warp_n = wid & 3;   // 0..3
    const int bx = blockIdx.x, by = blockIdx.y, bz = blockIdx.z;

    const float* At = A + bz * sA + (size_t)(by * 128) * ldA;
    const float* Bt = B + bz * sB + (size_t)(bx * TN) * ldB;

    wmma::fragment<wmma::accumulator, 16, 16, 8, float> acc[4][NT];
#pragma unroll
    for (int i = 0; i < 4; i++)
#pragma unroll
        for (int j = 0; j < NT; j++) wmma::fill_fragment(acc[i][j], 0.f);

    float4 ra[4], rb[NB];

    auto ldg = [&](int k0) {
#pragma unroll
        for (int i = 0; i < 4; i++) {
            int id = t + i * 256, r = id >> 3, c = id & 7;
            ra[i] = *(const float4*)&At[(size_t)r * ldA + k0 + c * 4];
        }
#pragma unroll
        for (int i = 0; i < NB; i++) {
            int id = t + i * 256, r = id >> 3, c = id & 7;
            rb[i] = *(const float4*)&Bt[(size_t)r * ldB + k0 + c * 4];
        }
    };
    auto split4 = [](float4 v, float* dh, float* dl) {
        float h;
        h = f2tf(v.x); dh[0] = h; dl[0] = f2tf(v.x - h);
        h = f2tf(v.y); dh[1] = h; dl[1] = f2tf(v.y - h);
        h = f2tf(v.z); dh[2] = h; dl[2] = f2tf(v.z - h);
        h = f2tf(v.w); dh[3] = h; dl[3] = f2tf(v.w - h);
    };
    auto sts = [&]() {
#pragma unroll
        for (int i = 0; i < 4; i++) {
            int id = t + i * 256, r = id >> 3, c = id & 7;
            split4(ra[i], &AsH[r * 36 + c * 4], &AsL[r * 36 + c * 4]);
        }
#pragma unroll
        for (int i = 0; i < NB; i++) {
            int id = t + i * 256, r = id >> 3, c = id & 7;
            split4(rb[i], &BsH[r * 36 + c * 4], &BsL[r * 36 + c * 4]);
        }
    };

    ldg(0);
    sts();
    __syncthreads();

    const int KB = K / 32;
    for (int kb = 0; kb < KB; kb++) {
        if (kb + 1 < KB) ldg((kb + 1) * 32);
#pragma unroll
        for (int ks = 0; ks < 4; ks++) {
            wmma::fragment<wmma::matrix_a, 16, 16, 8, wmma::precision::tf32,
                           wmma::row_major> faH[4], faL[4];
            wmma::fragment<wmma::matrix_b, 16, 16, 8, wmma::precision::tf32,
                           wmma::col_major> fbH[NT], fbL[NT];
#pragma unroll
            for (int i = 0; i < 4; i++) {
                int off = (warp_m * 64 + i * 16) * 36 + ks * 8;
                wmma::load_matrix_sync(faH[i], AsH + off, 36);
                wmma::load_matrix_sync(faL[i], AsL + off, 36);
            }
#pragma unroll
            for (int j = 0; j < NT; j++) {
                int off = (warp_n * (TN / 4) + j * 16) * 36 + ks * 8;
                wmma::load_matrix_sync(fbH[j], BsH + off, 36);
                wmma::load_matrix_sync(fbL[j], BsL + off, 36);
            }
#pragma unroll
            for (int i = 0; i < 4; i++)
#pragma unroll
                for (int j = 0; j < NT; j++) {
                    wmma::mma_sync(acc[i][j], faH[i], fbL[j], acc[i][j]);
                    wmma::mma_sync(acc[i][j], faL[i], fbH[j], acc[i][j]);
                    wmma::mma_sync(acc[i][j], faH[i], fbH[j], acc[i][j]);
                }
        }
        __syncthreads();
        if (kb + 1 < KB) {
            sts();
            __syncthreads();
        }
    }

    // ---------------- epilogue: stage acc in smem, then global writes -------
    float* Cs = sm;
    constexpr int LDCS = TN + 4;
#pragma unroll
    for (int i = 0; i < 4; i++)
#pragma unroll
        for (int j = 0; j < NT; j++)
            wmma::store_matrix_sync(
                Cs + (warp_m * 64 + i * 16) * LDCS + warp_n * (TN / 4) + j * 16,
                acc[i][j], LDCS, wmma::mem_row_major);
    __syncthreads();

    if (EPI == 1) {
        const int tok0 = by * 128;
        const int bglob = tok0 >> 12;
        const int tokin0 = tok0 & (NTOK - 1);
        for (int e = t; e < TN * 32; e += 256) {
            int j = e >> 5, tq = e & 31;
            float4 o;
            o.x = Cs[(tq * 4 + 0) * LDCS + j];
            o.y = Cs[(tq * 4 + 1) * LDCS + j];
            o.z = Cs[(tq * 4 + 2) * LDCS + j];
            o.w = Cs[(tq * 4 + 3) * LDCS + j];
            *(float4*)&C[((size_t)bglob * CC + bx * TN + j) * NTOK + tokin0 +
                         tq * 4] = o;
        }
    } else {
        const float g = (EPI == 2) ? gamma[0] : 0.f;
        for (int e = t; e < 128 * (TN / 4); e += 256) {
            int r = e / (TN / 4), c4 = e % (TN / 4);
            float4 o = *(float4*)&Cs[r * LDCS + c4 * 4];
            size_t base =
                bz * sC + (size_t)(by * 128 + r) * ldC + bx * TN + c4 * 4;
            if (EPI == 2) {
                float4 xr = *(const float4*)&xres[base];
                o.x = g * o.x + xr.x;
                o.y = g * o.y + xr.y;
                o.z = g * o.z + xr.z;
                o.w = g * o.w + xr.w;
            }
            *(float4*)&C[base] = o;
        }
    }
}

// ---------------- row softmax (in place) ------------------------------------
__global__ __launch_bounds__(256) void softmax_kernel(float* __restrict__ S) {
    __shared__ float red[8];
    const size_t row = blockIdx.x;
    float4* p = (float4*)(S + row * NTOK);
    const int t = threadIdx.x, w = t >> 5, lane = t & 31;

    float4 v[4];
#pragma unroll
    for (int j = 0; j < 4; j++) v[j] = p[t + j * 256];

    float mx = -3.4e38f;
#pragma unroll
    for (int j = 0; j < 4; j++)
        mx = fmaxf(mx, fmaxf(fmaxf(v[j].x, v[j].y), fmaxf(v[j].z, v[j].w)));
#pragma unroll
    for (int o = 16; o; o >>= 1) mx = fmaxf(mx, __shfl_xor_sync(~0u, mx, o));
    if (lane == 0) red[w] = mx;
    __syncthreads();
    mx = red[0];
#pragma unroll
    for (int i = 1; i < 8; i++) mx = fmaxf(mx, red[i]);
    __syncthreads();

    float sum = 0.f;
#pragma unroll
    for (int j = 0; j < 4; j++) {
        v[j].x = __expf(v[j].x - mx);
        v[j].y = __expf(v[j].y - mx);
        v[j].z = __expf(v[j].z - mx);
        v[j].w = __expf(v[j].w - mx);
        sum += v[j].x + v[j].y + v[j].z + v[j].w;
    }
#pragma unroll
    for (int o = 16; o; o >>= 1) sum += __shfl_xor_sync(~0u, sum, o);
    if (lane == 0) red[w] = sum;
    __syncthreads();
    sum = red[0];
#pragma unroll
    for (int i = 1; i < 8; i++) sum += red[i];
    float inv = 1.f / sum;
#pragma unroll
    for (int j = 0; j < 4; j++) {
        v[j].x *= inv;
        v[j].y *= inv;
        v[j].z *= inv;
        v[j].w *= inv;
        p[t + j * 256] = v[j];
    }
}

// ---------------------------------------------------------------------------
static inline int smem_bytes(int TN) {
    int buf = 2 * (128 + TN) * 36 * 4;      // hi+lo single stage
    int cs = 128 * (TN + 4) * 4;            // epilogue staging
    return buf > cs ? buf : cs;
}

extern "C" void kernel_launch(void* const* d_in, const int* in_sizes, int n_in,
                              void* d_out, int out_size) {
    const float* x = (const float*)d_in[0];
    const float* Wb = (const float*)d_in[1];
    const float* Wc = (const float*)d_in[2];
    const float* Wd = (const float*)d_in[3];
    const float* gamma = (const float*)d_in[4];
    float* out = (float*)d_out;

    float *qp, *kp, *vTp, *Sp, *WbT, *WcT, *WdT;
    cudaGetSymbolAddress((void**)&qp, g_q);
    cudaGetSymbolAddress((void**)&kp, g_k);
    cudaGetSymbolAddress((void**)&vTp, g_vT);
    cudaGetSymbolAddress((void**)&Sp, g_S);
    cudaGetSymbolAddress((void**)&WbT, g_WbT);
    cudaGetSymbolAddress((void**)&WcT, g_WcT);
    cudaGetSymbolAddress((void**)&WdT, g_WdT);

    cudaFuncSetAttribute(gemm_wmma<64, 0>,
                         cudaFuncAttributeMaxDynamicSharedMemorySize,
                         smem_bytes(64));
    cudaFuncSetAttribute(gemm_wmma<128, 0>,
                         cudaFuncAttributeMaxDynamicSharedMemorySize,
                         smem_bytes(128));
    cudaFuncSetAttribute(gemm_wmma<128, 1>,
                         cudaFuncAttributeMaxDynamicSharedMemorySize,
                         smem_bytes(128));
    cudaFuncSetAttribute(gemm_wmma<128, 2>,
                         cudaFuncAttributeMaxDynamicSharedMemorySize,
                         smem_bytes(128));

    // W transposes (K-major B operands)
    transpose_w<<<(CRD * CC + 255) / 256, 256>>>(Wb, WbT, CC, CRD);
    transpose_w<<<(CRD * CC + 255) / 256, 256>>>(Wc, WcT, CC, CRD);
    transpose_w<<<(CC * CC + 255) / 256, 256>>>(Wd, WdT, CC, CC);

    // q = X @ Wb, k = X @ Wc   (M=16384, N=64, K=512)
    gemm_wmma<64, 0><<<dim3(1, BNTOT / 128, 1), 256, smem_bytes(64)>>>(
        x, WbT, qp, CC, CC, CC, CRD, 0, 0, 0, nullptr, nullptr);
    gemm_wmma<64, 0><<<dim3(1, BNTOT / 128, 1), 256, smem_bytes(64)>>>(
        x, WcT, kp, CC, CC, CC, CRD, 0, 0, 0, nullptr, nullptr);
    // vT: v = X @ Wd stored transposed per batch (M=16384, N=512, K=512)
    gemm_wmma<128, 1><<<dim3(CC / 128, BNTOT / 128, 1), 256, smem_bytes(128)>>>(
        x, WdT, vTp, CC, CC, CC, 0, 0, 0, 0, nullptr, nullptr);
    // S = q k^T per batch (M=4096, N=4096, K=64)
    gemm_wmma<128, 0><<<dim3(NTOK / 128, NTOK / 128, B_), 256,
                        smem_bytes(128)>>>(
        qp, kp, Sp, CRD, CRD, CRD, NTOK, (size_t)NTOK * CRD,
        (size_t)NTOK * CRD, (size_t)NTOK * NTOK, nullptr, nullptr);
    // softmax rows
    softmax_kernel<<<B_ * NTOK, 256>>>(Sp);
    // out = gamma * (P @ v) + x  (M=4096, N=512, K=4096 per batch)
    gemm_wmma<128, 2><<<dim3(CC / 128, NTOK / 128, B_), 256,
                        smem_bytes(128)>>>(
        Sp, vTp, out, NTOK, NTOK, NTOK, CC, (size_t)NTOK * NTOK,
        (size_t)CC * NTOK, (size_t)NTOK * CC, x, gamma);
}

// round 6
// speedup vs baseline: 1.9565x; 1.9565x over previous
#include <cuda_runtime.h>
#include <mma.h>
#include <cstdint>

using namespace nvcuda;

// ---------------------------------------------------------------------------
// PAM via wmma tf32. Selective precision:
//   q,k,S GEMMs: 2-term tf32 split (3-MMA, ~21 mantissa bits) — scores feed exp
//   v,PV GEMMs:  plain tf32 (RNA-rounded inputs) — linear path, diluted by +x
// Pipeline: WT transposes -> q,k GEMM -> v GEMM (transposed store)
//   -> S = q k^T -> row softmax -> out = gamma*(P v) + x
// ---------------------------------------------------------------------------

#define B_    4
#define NTOK  4096
#define CC    512
#define CRD   64
#define BNTOT (B_ * NTOK)

__device__ float g_q[BNTOT * CRD];
__device__ float g_k[BNTOT * CRD];
__device__ float g_vT[(size_t)B_ * CC * NTOK];   // [b][c][tok]
__device__ float g_S[(size_t)B_ * NTOK * NTOK];  // [b][n][m]
__device__ float g_WbT[CRD * CC];
__device__ float g_WcT[CRD * CC];
__device__ float g_WdT[CC * CC];

__device__ __forceinline__ float f2tf(float f) {
    uint32_t u;
    asm("cvt.rna.tf32.f32 %0, %1;" : "=r"(u) : "f"(f));
    return __uint_as_float(u);
}

// ---------------- tiny W transpose ------------------------------------------
__global__ void transpose_w(const float* __restrict__ W, float* __restrict__ WT,
                            int K, int N) {
    int i = blockIdx.x * 256 + threadIdx.x;
    if (i < K * N) {
        int n = i / K, k = i - n * K;
        WT[i] = W[(size_t)k * N + n];
    }
}

// ---------------- wmma tf32 GEMM (optionally split) -------------------------
// D tile: 128 x TN. A: rows K-major [M,K]. B: rows K-major [Ntot,K].
// 256 threads, 8 warps 2(m) x 4(n); warp tile 64 x (TN/4). K-chunk 32.
// Double-buffered smem (2 stages), register-staged global prefetch,
// one __syncthreads per chunk.
// SPLIT: acc += Ahi*Blo + Alo*Bhi + Ahi*Bhi ; else acc += A*B (tf32-rounded)
// EPI 0: C = acc   EPI 1: transposed vT store   EPI 2: C = gamma*acc + x
template <int TN, int EPI, bool SPLIT>
__global__ __launch_bounds__(256) void gemm_wmma(
    const float* __restrict__ A, const float* __restrict__ B,
    float* __restrict__ C, int K, int ldA, int ldB, int ldC, size_t sA,
    size_t sB, size_t sC, const float* __restrict__ xres,
    const float* __restrict__ gamma) {
    extern __shared__ float sm[];
    constexpr int ASZ = 128 * 36;
    constexpr int BSZ = TN * 36;
    constexpr int STG = (SPLIT ? 2 : 1) * (ASZ + BSZ);  // floats per stage
    constexpr int NT = TN / 64;   // wmma n-tiles per warp
    constexpr int NB = TN / 32;   // B float4 loads per thread

    const int t = threadIdx.x;
    const int wid = t >> 5;
    const int warp_m = wid >> 2;
    const int warp_n = wid & 3;
    const int bx = blockIdx.x, by = blockIdx.y, bz = blockIdx.z;

    const float* At = A + bz * sA + (size_t)(by * 128) * ldA;
    const float* Bt = B + bz * sB + (size_t)(bx * TN) * ldB;

    wmma::fragment<wmma::accumulator, 16, 16, 8, float> acc[4][NT];
#pragma unroll
    for (int i = 0; i < 4; i++)
#pragma unroll
        for (int j = 0; j < NT; j++) wmma::fill_fragment(acc[i][j], 0.f);

    float4 ra[4], rb[NB];

    auto ldg = [&](int k0) {
#pragma unroll
        for (int i = 0; i < 4; i++) {
            int id = t + i * 256, r = id >> 3, c = id & 7;
            ra[i] = *(const float4*)&At[(size_t)r * ldA + k0 + c * 4];
        }
#pragma unroll
        for (int i = 0; i < NB; i++) {
            int id = t + i * 256, r = id >> 3, c = id & 7;
            rb[i] = *(const float4*)&Bt[(size_t)r * ldB + k0 + c * 4];
        }
    };

    auto sts = [&](int s) {
        float* base = sm + s * STG;
        if (SPLIT) {
            float* AsH = base;
            float* AsL = AsH + ASZ;
            float* BsH = AsL + ASZ;
            float* BsL = BsH + BSZ;
            auto split4 = [](float4 v, float* dh, float* dl) {
                float h;
                h = f2tf(v.x); dh[0] = h; dl[0] = f2tf(v.x - h);
                h = f2tf(v.y); dh[1] = h; dl[1] = f2tf(v.y - h);
                h = f2tf(v.z); dh[2] = h; dl[2] = f2tf(v.z - h);
                h = f2tf(v.w); dh[3] = h; dl[3] = f2tf(v.w - h);
            };
#pragma unroll
            for (int i = 0; i < 4; i++) {
                int id = t + i * 256, r = id >> 3, c = id & 7;
                split4(ra[i], &AsH[r * 36 + c * 4], &AsL[r * 36 + c * 4]);
            }
#pragma unroll
            for (int i = 0; i < NB; i++) {
                int id = t + i * 256, r = id >> 3, c = id & 7;
                split4(rb[i], &BsH[r * 36 + c * 4], &BsL[r * 36 + c * 4]);
            }
        } else {
            float* As = base;
            float* Bs = As + ASZ;
#pragma unroll
            for (int i = 0; i < 4; i++) {
                int id = t + i * 256, r = id >> 3, c = id & 7;
                float* d = &As[r * 36 + c * 4];
                d[0] = f2tf(ra[i].x);
                d[1] = f2tf(ra[i].y);
                d[2] = f2tf(ra[i].z);
                d[3] = f2tf(ra[i].w);
            }
#pragma unroll
            for (int i = 0; i < NB; i++) {
                int id = t + i * 256, r = id >> 3, c = id & 7;
                float* d = &Bs[r * 36 + c * 4];
                d[0] = f2tf(rb[i].x);
                d[1] = f2tf(rb[i].y);
                d[2] = f2tf(rb[i].z);
                d[3] = f2tf(rb[i].w);
            }
        }
    };

    ldg(0);
    sts(0);
    __syncthreads();

    const int KB = K / 32;
    for (int kb = 0; kb < KB; kb++) {
        const int p = kb & 1;
        if (kb + 1 < KB) ldg((kb + 1) * 32);

        float* base = sm + p * STG;
#pragma unroll
        for (int ks = 0; ks < 4; ks++) {
            if (SPLIT) {
                float* AsH = base;
                float* AsL = AsH + ASZ;
                float* BsH = AsL + ASZ;
                float* BsL = BsH + BSZ;
                wmma::fragment<wmma::matrix_a, 16, 16, 8,
                               wmma::precision::tf32, wmma::row_major>
                    faH[4], faL[4];
                wmma::fragment<wmma::matrix_b, 16, 16, 8,
                               wmma::precision::tf32, wmma::col_major>
                    fbH[NT], fbL[NT];
#pragma unroll
                for (int i = 0; i < 4; i++) {
                    int off = (warp_m * 64 + i * 16) * 36 + ks * 8;
                    wmma::load_matrix_sync(faH[i], AsH + off, 36);
                    wmma::load_matrix_sync(faL[i], AsL + off, 36);
                }
#pragma unroll
                for (int j = 0; j < NT; j++) {
                    int off = (warp_n * (TN / 4) + j * 16) * 36 + ks * 8;
                    wmma::load_matrix_sync(fbH[j], BsH + off, 36);
                    wmma::load_matrix_sync(fbL[j], BsL + off, 36);
                }
#pragma unroll
                for (int i = 0; i < 4; i++)
#pragma unroll
                    for (int j = 0; j < NT; j++) {
                        wmma::mma_sync(acc[i][j], faH[i], fbL[j], acc[i][j]);
                        wmma::mma_sync(acc[i][j], faL[i], fbH[j], acc[i][j]);
                        wmma::mma_sync(acc[i][j], faH[i], fbH[j], acc[i][j]);
                    }
            } else {
                float* As = base;
                float* Bs = As + ASZ;
                wmma::fragment<wmma::matrix_a, 16, 16, 8,
                               wmma::precision::tf32, wmma::row_major> fa[4];
                wmma::fragment<wmma::matrix_b, 16, 16, 8,
                               wmma::precision::tf32, wmma::col_major> fb[NT];
#pragma unroll
                for (int i = 0; i < 4; i++)
                    wmma::load_matrix_sync(
                        fa[i], As + (warp_m * 64 + i * 16) * 36 + ks * 8, 36);
#pragma unroll
                for (int j = 0; j < NT; j++)
                    wmma::load_matrix_sync(
                        fb[j], Bs + (warp_n * (TN / 4) + j * 16) * 36 + ks * 8,
                        36);
#pragma unroll
                for (int i = 0; i < 4; i++)
#pragma unroll
                    for (int j = 0; j < NT; j++)
                        wmma::mma_sync(acc[i][j], fa[i], fb[j], acc[i][j]);
            }
        }
        if (kb + 1 < KB) sts(p ^ 1);
        __syncthreads();
    }

    // ---------------- epilogue ----------------------------------------------
    float* Cs = sm;
    constexpr int LDCS = TN + 4;
#pragma unroll
    for (int i = 0; i < 4; i++)
#pragma unroll
        for (int j = 0; j < NT; j++)
            wmma::store_matrix_sync(
                Cs + (warp_m * 64 + i * 16) * LDCS + warp_n * (TN / 4) + j * 16,
                acc[i][j], LDCS, wmma::mem_row_major);
    __syncthreads();

    if (EPI == 1) {
        const int tok0 = by * 128;
        const int bglob = tok0 >> 12;
        const int tokin0 = tok0 & (NTOK - 1);
        for (int e = t; e < TN * 32; e += 256) {
            int j = e >> 5, tq = e & 31;
            float4 o;
            o.x = Cs[(tq * 4 + 0) * LDCS + j];
            o.y = Cs[(tq * 4 + 1) * LDCS + j];
            o.z = Cs[(tq * 4 + 2) * LDCS + j];
            o.w = Cs[(tq * 4 + 3) * LDCS + j];
            *(float4*)&C[((size_t)bglob * CC + bx * TN + j) * NTOK + tokin0 +
                         tq * 4] = o;
        }
    } else {
        const float g = (EPI == 2) ? gamma[0] : 0.f;
        for (int e = t; e < 128 * (TN / 4); e += 256) {
            int r = e / (TN / 4), c4 = e % (TN / 4);
            float4 o = *(float4*)&Cs[r * LDCS + c4 * 4];
            size_t base =
                bz * sC + (size_t)(by * 128 + r) * ldC + bx * TN + c4 * 4;
            if (EPI == 2) {
                float4 xr = *(const float4*)&xres[base];
                o.x = g * o.x + xr.x;
                o.y = g * o.y + xr.y;
                o.z = g * o.z + xr.z;
                o.w = g * o.w + xr.w;
            }
            *(float4*)&C[base] = o;
        }
    }
}

// ---------------- row softmax (in place) ------------------------------------
__global__ __launch_bounds__(256) void softmax_kernel(float* __restrict__ S) {
    __shared__ float red[8];
    const size_t row = blockIdx.x;
    float4* p = (float4*)(S + row * NTOK);
    const int t = threadIdx.x, w = t >> 5, lane = t & 31;

    float4 v[4];
#pragma unroll
    for (int j = 0; j < 4; j++) v[j] = p[t + j * 256];

    float mx = -3.4e38f;
#pragma unroll
    for (int j = 0; j < 4; j++)
        mx = fmaxf(mx, fmaxf(fmaxf(v[j].x, v[j].y), fmaxf(v[j].z, v[j].w)));
#pragma unroll
    for (int o = 16; o; o >>= 1) mx = fmaxf(mx, __shfl_xor_sync(~0u, mx, o));
    if (lane == 0) red[w] = mx;
    __syncthreads();
    mx = red[0];
#pragma unroll
    for (int i = 1; i < 8; i++) mx = fmaxf(mx, red[i]);
    __syncthreads();

    float sum = 0.f;
#pragma unroll
    for (int j = 0; j < 4; j++) {
        v[j].x = __expf(v[j].x - mx);
        v[j].y = __expf(v[j].y - mx);
        v[j].z = __expf(v[j].z - mx);
        v[j].w = __expf(v[j].w - mx);
        sum += v[j].x + v[j].y + v[j].z + v[j].w;
    }
#pragma unroll
    for (int o = 16; o; o >>= 1) sum += __shfl_xor_sync(~0u, sum, o);
    if (lane == 0) red[w] = sum;
    __syncthreads();
    sum = red[0];
#pragma unroll
    for (int i = 1; i < 8; i++) sum += red[i];
    float inv = 1.f / sum;
#pragma unroll
    for (int j = 0; j < 4; j++) {
        v[j].x *= inv;
        v[j].y *= inv;
        v[j].z *= inv;
        v[j].w *= inv;
        p[t + j * 256] = v[j];
    }
}

// ---------------------------------------------------------------------------
static inline int smem_bytes(int TN, bool split) {
    int stage = (split ? 2 : 1) * (128 + TN) * 36 * 4;
    int buf = 2 * stage;
    int cs = 128 * (TN + 4) * 4;
    return buf > cs ? buf : cs;
}

extern "C" void kernel_launch(void* const* d_in, const int* in_sizes, int n_in,
                              void* d_out, int out_size) {
    const float* x = (const float*)d_in[0];
    const float* Wb = (const float*)d_in[1];
    const float* Wc = (const float*)d_in[2];
    const float* Wd = (const float*)d_in[3];
    const float* gamma = (const float*)d_in[4];
    float* out = (float*)d_out;

    float *qp, *kp, *vTp, *Sp, *WbT, *WcT, *WdT;
    cudaGetSymbolAddress((void**)&qp, g_q);
    cudaGetSymbolAddress((void**)&kp, g_k);
    cudaGetSymbolAddress((void**)&vTp, g_vT);
    cudaGetSymbolAddress((void**)&Sp, g_S);
    cudaGetSymbolAddress((void**)&WbT, g_WbT);
    cudaGetSymbolAddress((void**)&WcT, g_WcT);
    cudaGetSymbolAddress((void**)&WdT, g_WdT);

    cudaFuncSetAttribute(gemm_wmma<64, 0, true>,
                         cudaFuncAttributeMaxDynamicSharedMemorySize,
                         smem_bytes(64, true));
    cudaFuncSetAttribute(gemm_wmma<128, 0, true>,
                         cudaFuncAttributeMaxDynamicSharedMemorySize,
                         smem_bytes(128, true));
    cudaFuncSetAttribute(gemm_wmma<128, 1, false>,
                         cudaFuncAttributeMaxDynamicSharedMemorySize,
                         smem_bytes(128, false));
    cudaFuncSetAttribute(gemm_wmma<128, 2, false>,
                         cudaFuncAttributeMaxDynamicSharedMemorySize,
                         smem_bytes(128, false));

    // W transposes (K-major B operands)
    transpose_w<<<(CRD * CC + 255) / 256, 256>>>(Wb, WbT, CC, CRD);
    transpose_w<<<(CRD * CC + 255) / 256, 256>>>(Wc, WcT, CC, CRD);
    transpose_w<<<(CC * CC + 255) / 256, 256>>>(Wd, WdT, CC, CC);

    // q = X @ Wb, k = X @ Wc   (split: feeds exp-sensitive scores)
    gemm_wmma<64, 0, true><<<dim3(1, BNTOT / 128, 1), 256,
                             smem_bytes(64, true)>>>(
        x, WbT, qp, CC, CC, CC, CRD, 0, 0, 0, nullptr, nullptr);
    gemm_wmma<64, 0, true><<<dim3(1, BNTOT / 128, 1), 256,
                             smem_bytes(64, true)>>>(
        x, WcT, kp, CC, CC, CC, CRD, 0, 0, 0, nullptr, nullptr);
    // vT: v = X @ Wd, transposed store (plain tf32)
    gemm_wmma<128, 1, false><<<dim3(CC / 128, BNTOT / 128, 1), 256,
                               smem_bytes(128, false)>>>(
        x, WdT, vTp, CC, CC, CC, 0, 0, 0, 0, nullptr, nullptr);
    // S = q k^T per batch (split)
    gemm_wmma<128, 0, true><<<dim3(NTOK / 128, NTOK / 128, B_), 256,
                              smem_bytes(128, true)>>>(
        qp, kp, Sp, CRD, CRD, CRD, NTOK, (size_t)NTOK * CRD,
        (size_t)NTOK * CRD, (size_t)NTOK * NTOK, nullptr, nullptr);
    // softmax rows
    softmax_kernel<<<B_ * NTOK, 256>>>(Sp);
    // out = gamma * (P @ v) + x  (plain tf32)
    gemm_wmma<128, 2, false><<<dim3(CC / 128, NTOK / 128, B_), 256,
                               smem_bytes(128, false)>>>(
        Sp, vTp, out, NTOK, NTOK, NTOK, CC, (size_t)NTOK * NTOK,
        (size_t)CC * NTOK, (size_t)NTOK * CC, x, gamma);
}

// round 7
// speedup vs baseline: 2.1335x; 1.0905x over previous
#include <cuda_runtime.h>
#include <mma.h>
#include <cstdint>

using namespace nvcuda;

// ---------------------------------------------------------------------------
// PAM via wmma tf32. Selective precision:
//   qk,S GEMMs: 2-term tf32 split (3-MMA, ~21 mantissa bits) — scores feed exp
//   v,PV GEMMs: plain tf32 (RNA-rounded inputs) — linear path, diluted by +x
// Pipeline: W transposes -> qk GEMM (fused q|k) -> v GEMM (transposed store)
//   -> S = q k^T -> row softmax -> out = gamma*(P v) + x
// ---------------------------------------------------------------------------

#define B_    4
#define NTOK  4096
#define CC    512
#define CRD   64
#define BNTOT (B_ * NTOK)

__device__ float g_qk[(size_t)BNTOT * 128];      // [tok][0:64)=q, [64:128)=k
__device__ float g_vT[(size_t)B_ * CC * NTOK];   // [b][c][tok]
__device__ float g_S[(size_t)B_ * NTOK * NTOK];  // [b][n][m]
__device__ float g_WqkT[128 * CC];               // rows 0-63 Wb^T, 64-127 Wc^T
__device__ float g_WdT[CC * CC];

__device__ __forceinline__ float f2tf(float f) {
    uint32_t u;
    asm("cvt.rna.tf32.f32 %0, %1;" : "=r"(u) : "f"(f));
    return __uint_as_float(u);
}

// ---------------- weight transposes -----------------------------------------
__global__ void transpose_w(const float* __restrict__ W, float* __restrict__ WT,
                            int K, int N) {
    int i = blockIdx.x * 256 + threadIdx.x;
    if (i < K * N) {
        int n = i / K, k = i - n * K;
        WT[i] = W[(size_t)k * N + n];
    }
}
__global__ void transpose_wqk(const float* __restrict__ Wb,
                              const float* __restrict__ Wc,
                              float* __restrict__ WT) {
    int i = blockIdx.x * 256 + threadIdx.x;  // i over 128*512
    if (i < 128 * CC) {
        int n = i / CC, k = i - n * CC;
        WT[i] = (n < CRD) ? Wb[(size_t)k * CRD + n]
                          : Wc[(size_t)k * CRD + (n - CRD)];
    }
}

// ---------------- wmma tf32 GEMM (optionally split) -------------------------
// D tile: 128 x TN. A: rows K-major [M,K]. B: rows K-major [Ntot,K].
// 256 threads, 8 warps 2(m) x 4(n); warp tile 64 x (TN/4). K-chunk 32.
// Double-buffered smem, register-staged global prefetch, 1 sync per chunk.
// SPLIT: acc += Ahi*Blo + Alo*Bhi + Ahi*Bhi ; else acc += A*B (tf32-rounded)
// EPI 0: C = acc   EPI 1: transposed vT store   EPI 2: C = gamma*acc + x
template <int TN, int EPI, bool SPLIT>
__global__ __launch_bounds__(256) void gemm_wmma(
    const float* __restrict__ A, const float* __restrict__ B,
    float* __restrict__ C, int K, int ldA, int ldB, int ldC, size_t sA,
    size_t sB, size_t sC, const float* __restrict__ xres,
    const float* __restrict__ gamma) {
    extern __shared__ float sm[];
    constexpr int ASZ = 128 * 36;
    constexpr int BSZ = TN * 36;
    constexpr int STG = (SPLIT ? 2 : 1) * (ASZ + BSZ);  // floats per stage
    constexpr int NT = TN / 64;   // wmma n-tiles per warp
    constexpr int NB = TN / 32;   // B float4 loads per thread

    const int t = threadIdx.x;
    const int wid = t >> 5;
    const int warp_m = wid >> 2;
    const int warp_n = wid & 3;
    const int bx = blockIdx.x, by = blockIdx.y, bz = blockIdx.z;

    const float* At = A + bz * sA + (size_t)(by * 128) * ldA;
    const float* Bt = B + bz * sB + (size_t)(bx * TN) * ldB;

    wmma::fragment<wmma::accumulator, 16, 16, 8, float> acc[4][NT];
#pragma unroll
    for (int i = 0; i < 4; i++)
#pragma unroll
        for (int j = 0; j < NT; j++) wmma::fill_fragment(acc[i][j], 0.f);

    float4 ra[4], rb[NB];

    auto ldg = [&](int k0) {
#pragma unroll
        for (int i = 0; i < 4; i++) {
            int id = t + i * 256, r = id >> 3, c = id & 7;
            ra[i] = *(const float4*)&At[(size_t)r * ldA + k0 + c * 4];
        }
#pragma unroll
        for (int i = 0; i < NB; i++) {
            int id = t + i * 256, r = id >> 3, c = id & 7;
            rb[i] = *(const float4*)&Bt[(size_t)r * ldB + k0 + c * 4];
        }
    };

    auto sts = [&](int s) {
        float* base = sm + s * STG;
        if (SPLIT) {
            float* AsH = base;
            float* AsL = AsH + ASZ;
            float* BsH = AsL + ASZ;
            float* BsL = BsH + BSZ;
            auto split4 = [](float4 v, float* dh, float* dl) {
                float h;
                h = f2tf(v.x); dh[0] = h; dl[0] = f2tf(v.x - h);
                h = f2tf(v.y); dh[1] = h; dl[1] = f2tf(v.y - h);
                h = f2tf(v.z); dh[2] = h; dl[2] = f2tf(v.z - h);
                h = f2tf(v.w); dh[3] = h; dl[3] = f2tf(v.w - h);
            };
#pragma unroll
            for (int i = 0; i < 4; i++) {
                int id = t + i * 256, r = id >> 3, c = id & 7;
                split4(ra[i], &AsH[r * 36 + c * 4], &AsL[r * 36 + c * 4]);
            }
#pragma unroll
            for (int i = 0; i < NB; i++) {
                int id = t + i * 256, r = id >> 3, c = id & 7;
                split4(rb[i], &BsH[r * 36 + c * 4], &BsL[r * 36 + c * 4]);
            }
        } else {
            float* As = base;
            float* Bs = As + ASZ;
#pragma unroll
            for (int i = 0; i < 4; i++) {
                int id = t + i * 256, r = id >> 3, c = id & 7;
                float* d = &As[r * 36 + c * 4];
                d[0] = f2tf(ra[i].x);
                d[1] = f2tf(ra[i].y);
                d[2] = f2tf(ra[i].z);
                d[3] = f2tf(ra[i].w);
            }
#pragma unroll
            for (int i = 0; i < NB; i++) {
                int id = t + i * 256, r = id >> 3, c = id & 7;
                float* d = &Bs[r * 36 + c * 4];
                d[0] = f2tf(rb[i].x);
                d[1] = f2tf(rb[i].y);
                d[2] = f2tf(rb[i].z);
                d[3] = f2tf(rb[i].w);
            }
        }
    };

    ldg(0);
    sts(0);
    __syncthreads();

    const int KB = K / 32;
    for (int kb = 0; kb < KB; kb++) {
        const int p = kb & 1;
        if (kb + 1 < KB) ldg((kb + 1) * 32);

        float* base = sm + p * STG;
#pragma unroll
        for (int ks = 0; ks < 4; ks++) {
            if (SPLIT) {
                float* AsH = base;
                float* AsL = AsH + ASZ;
                float* BsH = AsL + ASZ;
                float* BsL = BsH + BSZ;
                wmma::fragment<wmma::matrix_a, 16, 16, 8,
                               wmma::precision::tf32, wmma::row_major>
                    faH[4], faL[4];
                wmma::fragment<wmma::matrix_b, 16, 16, 8,
                               wmma::precision::tf32, wmma::col_major>
                    fbH[NT], fbL[NT];
#pragma unroll
                for (int i = 0; i < 4; i++) {
                    int off = (warp_m * 64 + i * 16) * 36 + ks * 8;
                    wmma::load_matrix_sync(faH[i], AsH + off, 36);
                    wmma::load_matrix_sync(faL[i], AsL + off, 36);
                }
#pragma unroll
                for (int j = 0; j < NT; j++) {
                    int off = (warp_n * (TN / 4) + j * 16) * 36 + ks * 8;
                    wmma::load_matrix_sync(fbH[j], BsH + off, 36);
                    wmma::load_matrix_sync(fbL[j], BsL + off, 36);
                }
#pragma unroll
                for (int i = 0; i < 4; i++)
#pragma unroll
                    for (int j = 0; j < NT; j++) {
                        wmma::mma_sync(acc[i][j], faH[i], fbL[j], acc[i][j]);
                        wmma::mma_sync(acc[i][j], faL[i], fbH[j], acc[i][j]);
                        wmma::mma_sync(acc[i][j], faH[i], fbH[j], acc[i][j]);
                    }
            } else {
                float* As = base;
                float* Bs = As + ASZ;
                wmma::fragment<wmma::matrix_a, 16, 16, 8,
                               wmma::precision::tf32, wmma::row_major> fa[4];
                wmma::fragment<wmma::matrix_b, 16, 16, 8,
                               wmma::precision::tf32, wmma::col_major> fb[NT];
#pragma unroll
                for (int i = 0; i < 4; i++)
                    wmma::load_matrix_sync(
                        fa[i], As + (warp_m * 64 + i * 16) * 36 + ks * 8, 36);
#pragma unroll
                for (int j = 0; j < NT; j++)
                    wmma::load_matrix_sync(
                        fb[j], Bs + (warp_n * (TN / 4) + j * 16) * 36 + ks * 8,
                        36);
#pragma unroll
                for (int i = 0; i < 4; i++)
#pragma unroll
                    for (int j = 0; j < NT; j++)
                        wmma::mma_sync(acc[i][j], fa[i], fb[j], acc[i][j]);
            }
        }
        if (kb + 1 < KB) sts(p ^ 1);
        __syncthreads();
    }

    // ---------------- epilogue ----------------------------------------------
    float* Cs = sm;
    constexpr int LDCS = TN + 4;
#pragma unroll
    for (int i = 0; i < 4; i++)
#pragma unroll
        for (int j = 0; j < NT; j++)
            wmma::store_matrix_sync(
                Cs + (warp_m * 64 + i * 16) * LDCS + warp_n * (TN / 4) + j * 16,
                acc[i][j], LDCS, wmma::mem_row_major);
    __syncthreads();

    if (EPI == 1) {
        const int tok0 = by * 128;
        const int bglob = tok0 >> 12;
        const int tokin0 = tok0 & (NTOK - 1);
        for (int e = t; e < TN * 32; e += 256) {
            int j = e >> 5, tq = e & 31;
            float4 o;
            o.x = Cs[(tq * 4 + 0) * LDCS + j];
            o.y = Cs[(tq * 4 + 1) * LDCS + j];
            o.z = Cs[(tq * 4 + 2) * LDCS + j];
            o.w = Cs[(tq * 4 + 3) * LDCS + j];
            *(float4*)&C[((size_t)bglob * CC + bx * TN + j) * NTOK + tokin0 +
                         tq * 4] = o;
        }
    } else {
        const float g = (EPI == 2) ? gamma[0] : 0.f;
        for (int e = t; e < 128 * (TN / 4); e += 256) {
            int r = e / (TN / 4), c4 = e % (TN / 4);
            float4 o = *(float4*)&Cs[r * LDCS + c4 * 4];
            size_t base =
                bz * sC + (size_t)(by * 128 + r) * ldC + bx * TN + c4 * 4;
            if (EPI == 2) {
                float4 xr = *(const float4*)&xres[base];
                o.x = g * o.x + xr.x;
                o.y = g * o.y + xr.y;
                o.z = g * o.z + xr.z;
                o.w = g * o.w + xr.w;
            }
            *(float4*)&C[base] = o;
        }
    }
}

// ---------------- row softmax (in place) ------------------------------------
__global__ __launch_bounds__(256) void softmax_kernel(float* __restrict__ S) {
    __shared__ float red[8];
    const size_t row = blockIdx.x;
    float4* p = (float4*)(S + row * NTOK);
    const int t = threadIdx.x, w = t >> 5, lane = t & 31;

    float4 v[4];
#pragma unroll
    for (int j = 0; j < 4; j++) v[j] = p[t + j * 256];

    float mx = -3.4e38f;
#pragma unroll
    for (int j = 0; j < 4; j++)
        mx = fmaxf(mx, fmaxf(fmaxf(v[j].x, v[j].y), fmaxf(v[j].z, v[j].w)));
#pragma unroll
    for (int o = 16; o; o >>= 1) mx = fmaxf(mx, __shfl_xor_sync(~0u, mx, o));
    if (lane == 0) red[w] = mx;
    __syncthreads();
    mx = red[0];
#pragma unroll
    for (int i = 1; i < 8; i++) mx = fmaxf(mx, red[i]);
    __syncthreads();

    float sum = 0.f;
#pragma unroll
    for (int j = 0; j < 4; j++) {
        v[j].x = __expf(v[j].x - mx);
        v[j].y = __expf(v[j].y - mx);
        v[j].z = __expf(v[j].z - mx);
        v[j].w = __expf(v[j].w - mx);
        sum += v[j].x + v[j].y + v[j].z + v[j].w;
    }
#pragma unroll
    for (int o = 16; o; o >>= 1) sum += __shfl_xor_sync(~0u, sum, o);
    if (lane == 0) red[w] = sum;
    __syncthreads();
    sum = red[0];
#pragma unroll
    for (int i = 1; i < 8; i++) sum += red[i];
    float inv = 1.f / sum;
#pragma unroll
    for (int j = 0; j < 4; j++) {
        v[j].x *= inv;
        v[j].y *= inv;
        v[j].z *= inv;
        v[j].w *= inv;
        p[t + j * 256] = v[j];
    }
}

// ---------------------------------------------------------------------------
static inline int smem_bytes(int TN, bool split) {
    int stage = (split ? 2 : 1) * (128 + TN) * 36 * 4;
    int buf = 2 * stage;
    int cs = 128 * (TN + 4) * 4;
    return buf > cs ? buf : cs;
}

extern "C" void kernel_launch(void* const* d_in, const int* in_sizes, int n_in,
                              void* d_out, int out_size) {
    const float* x = (const float*)d_in[0];
    const float* Wb = (const float*)d_in[1];
    const float* Wc = (const float*)d_in[2];
    const float* Wd = (const float*)d_in[3];
    const float* gamma = (const float*)d_in[4];
    float* out = (float*)d_out;

    float *qkp, *vTp, *Sp, *WqkT, *WdT;
    cudaGetSymbolAddress((void**)&qkp, g_qk);
    cudaGetSymbolAddress((void**)&vTp, g_vT);
    cudaGetSymbolAddress((void**)&Sp, g_S);
    cudaGetSymbolAddress((void**)&WqkT, g_WqkT);
    cudaGetSymbolAddress((void**)&WdT, g_WdT);

    cudaFuncSetAttribute(gemm_wmma<128, 0, true>,
                         cudaFuncAttributeMaxDynamicSharedMemorySize,
                         smem_bytes(128, true));
    cudaFuncSetAttribute(gemm_wmma<256, 1, false>,
                         cudaFuncAttributeMaxDynamicSharedMemorySize,
                         smem_bytes(256, false));
    cudaFuncSetAttribute(gemm_wmma<256, 2, false>,
                         cudaFuncAttributeMaxDynamicSharedMemorySize,
                         smem_bytes(256, false));

    // weight transposes (K-major B operands); qk fused
    transpose_wqk<<<(128 * CC + 255) / 256, 256>>>(Wb, Wc, WqkT);
    transpose_w<<<(CC * CC + 255) / 256, 256>>>(Wd, WdT, CC, CC);

    // qk = X @ [Wb|Wc]  (split; M=16384, N=128, K=512)
    gemm_wmma<128, 0, true><<<dim3(1, BNTOT / 128, 1), 256,
                              smem_bytes(128, true)>>>(
        x, WqkT, qkp, CC, CC, CC, 128, 0, 0, 0, nullptr, nullptr);
    // vT: v = X @ Wd, transposed store (plain tf32; M=16384, N=512, K=512)
    gemm_wmma<256, 1, false><<<dim3(CC / 256, BNTOT / 128, 1), 256,
                               smem_bytes(256, false)>>>(
        x, WdT, vTp, CC, CC, CC, 0, 0, 0, 0, nullptr, nullptr);
    // S = q k^T per batch (split; A=qk cols 0-63, B=qk cols 64-127, K=64)
    gemm_wmma<128, 0, true><<<dim3(NTOK / 128, NTOK / 128, B_), 256,
                              smem_bytes(128, true)>>>(
        qkp, qkp + CRD, Sp, CRD, 128, 128, NTOK, (size_t)NTOK * 128,
        (size_t)NTOK * 128, (size_t)NTOK * NTOK, nullptr, nullptr);
    // softmax rows
    softmax_kernel<<<B_ * NTOK, 256>>>(Sp);
    // out = gamma * (P @ v) + x  (plain tf32; M=4096, N=512, K=4096 per batch)
    gemm_wmma<256, 2, false><<<dim3(CC / 256, NTOK / 128, B_), 256,
                               smem_bytes(256, false)>>>(
        Sp, vTp, out, NTOK, NTOK, NTOK, CC, (size_t)NTOK * NTOK,
        (size_t)CC * NTOK, (size_t)NTOK * CC, x, gamma);
}

// round 8
// speedup vs baseline: 2.2635x; 1.0610x over previous
#include <cuda_runtime.h>
#include <mma.h>
#include <cstdint>

using namespace nvcuda;

// ---------------------------------------------------------------------------
// PAM, wmma tf32, cp.async pipelines. All GEMM inputs pre-rounded to tf32
// (RNA) at producer time; split (hi/lo) GEMMs for the exp-sensitive path.
//   round_x, W transposes -> qk GEMM (split, hi/lo out) -> v GEMM (async,
//   transposed rounded store) -> S = q k^T (async split) -> softmax (rounded
//   P) -> out = gamma*(P v) + x (async plain)
// ---------------------------------------------------------------------------

#define B_    4
#define NTOK  4096
#define CC    512
#define CRD   64
#define BNTOT (B_ * NTOK)

__device__ float g_qkH[(size_t)BNTOT * 128];
__device__ float g_qkL[(size_t)BNTOT * 128];
__device__ float g_xr[(size_t)BNTOT * CC];       // tf32-rounded x
__device__ float g_vT[(size_t)B_ * CC * NTOK];   // [b][c][tok], rounded
__device__ float g_S[(size_t)B_ * NTOK * NTOK];  // scores -> rounded probs
__device__ float g_WqkT[128 * CC];               // raw (split in-kernel)
__device__ float g_WdT[CC * CC];                 // rounded

__device__ __forceinline__ float f2tf(float f) {
    uint32_t u;
    asm("cvt.rna.tf32.f32 %0, %1;" : "=r"(u) : "f"(f));
    return __uint_as_float(u);
}
__device__ __forceinline__ uint32_t smem_u32(const void* p) {
    uint32_t a;
    asm("{ .reg .u64 t; cvta.to.shared.u64 t, %1; cvt.u32.u64 %0, t; }"
        : "=r"(a) : "l"(p));
    return a;
}
__device__ __forceinline__ void cp16(uint32_t saddr, const void* g) {
    asm volatile("cp.async.cg.shared.global [%0], [%1], 16;" ::"r"(saddr),
                 "l"(g));
}
#define CP_COMMIT() asm volatile("cp.async.commit_group;" ::: "memory")
#define CP_WAIT0()  asm volatile("cp.async.wait_group 0;" ::: "memory")

// ---------------- producers --------------------------------------------------
__global__ void round_x(const float4* __restrict__ in, float4* __restrict__ o,
                        int n4) {
    int i = blockIdx.x * 256 + threadIdx.x;
    if (i < n4) {
        float4 v = in[i];
        v.x = f2tf(v.x); v.y = f2tf(v.y); v.z = f2tf(v.z); v.w = f2tf(v.w);
        o[i] = v;
    }
}
__global__ void transpose_w_round(const float* __restrict__ W,
                                  float* __restrict__ WT, int K, int N) {
    int i = blockIdx.x * 256 + threadIdx.x;
    if (i < K * N) {
        int n = i / K, k = i - n * K;
        WT[i] = f2tf(W[(size_t)k * N + n]);
    }
}
__global__ void transpose_wqk(const float* __restrict__ Wb,
                              const float* __restrict__ Wc,
                              float* __restrict__ WT) {
    int i = blockIdx.x * 256 + threadIdx.x;
    if (i < 128 * CC) {
        int n = i / CC, k = i - n * CC;
        WT[i] = (n < CRD) ? Wb[(size_t)k * CRD + n]
                          : Wc[(size_t)k * CRD + (n - CRD)];
    }
}

// ---------------- qk GEMM: register-staged split, hi/lo output ---------------
// D 128x128, A=x [M,512], B=WqkT [128,512]. Outputs CH/CL tf32-exact pairs.
__global__ __launch_bounds__(256) void gemm_qk(const float* __restrict__ A,
                                               const float* __restrict__ B,
                                               float* __restrict__ CH,
                                               float* __restrict__ CL) {
    extern __shared__ float sm[];
    constexpr int ASZ = 128 * 36, BSZ = 128 * 36;
    constexpr int STG = 2 * (ASZ + BSZ);
    const int t = threadIdx.x, wid = t >> 5;
    const int warp_m = wid >> 2, warp_n = wid & 3;
    const int by = blockIdx.y;

    const float* At = A + (size_t)(by * 128) * CC;

    wmma::fragment<wmma::accumulator, 16, 16, 8, float> acc[4][2];
#pragma unroll
    for (int i = 0; i < 4; i++)
#pragma unroll
        for (int j = 0; j < 2; j++) wmma::fill_fragment(acc[i][j], 0.f);

    float4 ra[4], rb[4];
    auto ldg = [&](int k0) {
#pragma unroll
        for (int i = 0; i < 4; i++) {
            int id = t + i * 256, r = id >> 3, c = id & 7;
            ra[i] = *(const float4*)&At[(size_t)r * CC + k0 + c * 4];
            rb[i] = *(const float4*)&B[(size_t)r * CC + k0 + c * 4];
        }
    };
    auto sts = [&](int s) {
        float* AsH = sm + s * STG;
        float* AsL = AsH + ASZ;
        float* BsH = AsL + ASZ;
        float* BsL = BsH + BSZ;
        auto split4 = [](float4 v, float* dh, float* dl) {
            float h;
            h = f2tf(v.x); dh[0] = h; dl[0] = f2tf(v.x - h);
            h = f2tf(v.y); dh[1] = h; dl[1] = f2tf(v.y - h);
            h = f2tf(v.z); dh[2] = h; dl[2] = f2tf(v.z - h);
            h = f2tf(v.w); dh[3] = h; dl[3] = f2tf(v.w - h);
        };
#pragma unroll
        for (int i = 0; i < 4; i++) {
            int id = t + i * 256, r = id >> 3, c = id & 7;
            split4(ra[i], &AsH[r * 36 + c * 4], &AsL[r * 36 + c * 4]);
            split4(rb[i], &BsH[r * 36 + c * 4], &BsL[r * 36 + c * 4]);
        }
    };

    ldg(0);
    sts(0);
    __syncthreads();

    const int KB = CC / 32;
    for (int kb = 0; kb < KB; kb++) {
        const int p = kb & 1;
        if (kb + 1 < KB) ldg((kb + 1) * 32);
        float* AsH = sm + p * STG;
        float* AsL = AsH + ASZ;
        float* BsH = AsL + ASZ;
        float* BsL = BsH + BSZ;
#pragma unroll
        for (int ks = 0; ks < 4; ks++) {
            wmma::fragment<wmma::matrix_a, 16, 16, 8, wmma::precision::tf32,
                           wmma::row_major> faH[4], faL[4];
            wmma::fragment<wmma::matrix_b, 16, 16, 8, wmma::precision::tf32,
                           wmma::col_major> fbH[2], fbL[2];
#pragma unroll
            for (int i = 0; i < 4; i++) {
                int off = (warp_m * 64 + i * 16) * 36 + ks * 8;
                wmma::load_matrix_sync(faH[i], AsH + off, 36);
                wmma::load_matrix_sync(faL[i], AsL + off, 36);
            }
#pragma unroll
            for (int j = 0; j < 2; j++) {
                int off = (warp_n * 32 + j * 16) * 36 + ks * 8;
                wmma::load_matrix_sync(fbH[j], BsH + off, 36);
                wmma::load_matrix_sync(fbL[j], BsL + off, 36);
            }
#pragma unroll
            for (int i = 0; i < 4; i++)
#pragma unroll
                for (int j = 0; j < 2; j++) {
                    wmma::mma_sync(acc[i][j], faH[i], fbL[j], acc[i][j]);
                    wmma::mma_sync(acc[i][j], faL[i], fbH[j], acc[i][j]);
                    wmma::mma_sync(acc[i][j], faH[i], fbH[j], acc[i][j]);
                }
        }
        if (kb + 1 < KB) sts(p ^ 1);
        __syncthreads();
    }

    float* Cs = sm;
#pragma unroll
    for (int i = 0; i < 4; i++)
#pragma unroll
        for (int j = 0; j < 2; j++)
            wmma::store_matrix_sync(
                Cs + (warp_m * 64 + i * 16) * 132 + warp_n * 32 + j * 16,
                acc[i][j], 132, wmma::mem_row_major);
    __syncthreads();
    for (int e = t; e < 128 * 32; e += 256) {
        int r = e >> 5, c4 = e & 31;
        float4 v = *(float4*)&Cs[r * 132 + c4 * 4];
        float4 h, l;
        h.x = f2tf(v.x); l.x = f2tf(v.x - h.x);
        h.y = f2tf(v.y); l.y = f2tf(v.y - h.y);
        h.z = f2tf(v.z); l.z = f2tf(v.z - h.z);
        h.w = f2tf(v.w); l.w = f2tf(v.w - h.w);
        size_t idx = (size_t)(by * 128 + r) * 128 + c4 * 4;
        *(float4*)&CH[idx] = h;
        *(float4*)&CL[idx] = l;
    }
}

// ---------------- cp.async GEMM engine ---------------------------------------
// Inputs must be tf32-exact in gmem. D 128xTN, 8 warps 2x4, warp 64x(TN/4).
// SPLIT: A/B have hi+lo buffers, acc += AH*BL + AL*BH + AH*BH.
// EPI 0: C = acc   EPI 1: transposed vT store (rounded)   EPI 2: gamma*acc+x
template <int TN, int EPI, bool SPLIT>
__global__ __launch_bounds__(256) void gemm_async(
    const float* __restrict__ AH, const float* __restrict__ AL,
    const float* __restrict__ BH, const float* __restrict__ BL,
    float* __restrict__ C, int K, int ldA, int ldB, int ldC, size_t sA,
    size_t sB, size_t sC, const float* __restrict__ xres,
    const float* __restrict__ gamma) {
    extern __shared__ float sm[];
    constexpr int ASZ = 128 * 36, BSZ = TN * 36;
    constexpr int CMP = SPLIT ? 2 : 1;
    constexpr int STG = CMP * (ASZ + BSZ);     // floats per stage
    constexpr int NT = TN / 64;
    constexpr int NB = TN / 32;

    const int t = threadIdx.x, wid = t >> 5;
    const int warp_m = wid >> 2, warp_n = wid & 3;
    const int bx = blockIdx.x, by = blockIdx.y, bz = blockIdx.z;
    const uint32_t smb = smem_u32(sm);

    const float* AtH = AH + bz * sA + (size_t)(by * 128) * ldA;
    const float* BtH = BH + bz * sB + (size_t)(bx * TN) * ldB;
    const float* AtL = SPLIT ? AL + bz * sA + (size_t)(by * 128) * ldA : nullptr;
    const float* BtL = SPLIT ? BL + bz * sB + (size_t)(bx * TN) * ldB : nullptr;

    wmma::fragment<wmma::accumulator, 16, 16, 8, float> acc[4][NT];
#pragma unroll
    for (int i = 0; i < 4; i++)
#pragma unroll
        for (int j = 0; j < NT; j++) wmma::fill_fragment(acc[i][j], 0.f);

    auto issue = [&](int s, int k0) {
        uint32_t ab = smb + s * STG * 4;
        uint32_t bb = ab + CMP * ASZ * 4;
#pragma unroll
        for (int i = 0; i < 4; i++) {
            int id = t + i * 256, r = id >> 3, c = id & 7;
            uint32_t so = (r * 36 + c * 4) * 4;
            cp16(ab + so, AtH + (size_t)r * ldA + k0 + c * 4);
            if (SPLIT) cp16(ab + ASZ * 4 + so, AtL + (size_t)r * ldA + k0 + c * 4);
        }
#pragma unroll
        for (int i = 0; i < NB; i++) {
            int id = t + i * 256, r = id >> 3, c = id & 7;
            uint32_t so = (r * 36 + c * 4) * 4;
            cp16(bb + so, BtH + (size_t)r * ldB + k0 + c * 4);
            if (SPLIT) cp16(bb + BSZ * 4 + so, BtL + (size_t)r * ldB + k0 + c * 4);
        }
    };

    issue(0, 0);
    CP_COMMIT();
    CP_WAIT0();
    __syncthreads();

    const int KB = K / 32;
    for (int kb = 0; kb < KB; kb++) {
        const int p = kb & 1;
        if (kb + 1 < KB) {
            issue(p ^ 1, (kb + 1) * 32);
            CP_COMMIT();
        }
        float* AsH = sm + p * STG;
        float* AsL = AsH + ASZ;
        float* BsH = AsH + CMP * ASZ;
        float* BsL = BsH + BSZ;
#pragma unroll
        for (int ks = 0; ks < 4; ks++) {
            if (SPLIT) {
                wmma::fragment<wmma::matrix_a, 16, 16, 8,
                               wmma::precision::tf32, wmma::row_major>
                    faH[4], faL[4];
                wmma::fragment<wmma::matrix_b, 16, 16, 8,
                               wmma::precision::tf32, wmma::col_major>
                    fbH[NT], fbL[NT];
#pragma unroll
                for (int i = 0; i < 4; i++) {
                    int off = (warp_m * 64 + i * 16) * 36 + ks * 8;
                    wmma::load_matrix_sync(faH[i], AsH + off, 36);
                    wmma::load_matrix_sync(faL[i], AsL + off, 36);
                }
#pragma unroll
                for (int j = 0; j < NT; j++) {
                    int off = (warp_n * (TN / 4) + j * 16) * 36 + ks * 8;
                    wmma::load_matrix_sync(fbH[j], BsH + off, 36);
                    wmma::load_matrix_sync(fbL[j], BsL + off, 36);
                }
#pragma unroll
                for (int i = 0; i < 4; i++)
#pragma unroll
                    for (int j = 0; j < NT; j++) {
                        wmma::mma_sync(acc[i][j], faH[i], fbL[j], acc[i][j]);
                        wmma::mma_sync(acc[i][j], faL[i], fbH[j], acc[i][j]);
                        wmma::mma_sync(acc[i][j], faH[i], fbH[j], acc[i][j]);
                    }
            } else {
                wmma::fragment<wmma::matrix_a, 16, 16, 8,
                               wmma::precision::tf32, wmma::row_major> fa[4];
                wmma::fragment<wmma::matrix_b, 16, 16, 8,
                               wmma::precision::tf32, wmma::col_major> fb[NT];
#pragma unroll
                for (int i = 0; i < 4; i++)
                    wmma::load_matrix_sync(
                        fa[i], AsH + (warp_m * 64 + i * 16) * 36 + ks * 8, 36);
#pragma unroll
                for (int j = 0; j < NT; j++)
                    wmma::load_matrix_sync(
                        fb[j], BsH + (warp_n * (TN / 4) + j * 16) * 36 + ks * 8,
                        36);
#pragma unroll
                for (int i = 0; i < 4; i++)
#pragma unroll
                    for (int j = 0; j < NT; j++)
                        wmma::mma_sync(acc[i][j], fa[i], fb[j], acc[i][j]);
            }
        }
        if (kb + 1 < KB) CP_WAIT0();
        __syncthreads();
    }

    // ---------------- epilogue ----------------------------------------------
    float* Cs = sm;
    constexpr int LDCS = TN + 4;
#pragma unroll
    for (int i = 0; i < 4; i++)
#pragma unroll
        for (int j = 0; j < NT; j++)
            wmma::store_matrix_sync(
                Cs + (warp_m * 64 + i * 16) * LDCS + warp_n * (TN / 4) + j * 16,
                acc[i][j], LDCS, wmma::mem_row_major);
    __syncthreads();

    if (EPI == 1) {
        const int tok0 = by * 128;
        const int bglob = tok0 >> 12;
        const int tokin0 = tok0 & (NTOK - 1);
        for (int e = t; e < TN * 32; e += 256) {
            int j = e >> 5, tq = e & 31;
            float4 o;
            o.x = f2tf(Cs[(tq * 4 + 0) * LDCS + j]);
            o.y = f2tf(Cs[(tq * 4 + 1) * LDCS + j]);
            o.z = f2tf(Cs[(tq * 4 + 2) * LDCS + j]);
            o.w = f2tf(Cs[(tq * 4 + 3) * LDCS + j]);
            *(float4*)&C[((size_t)bglob * CC + bx * TN + j) * NTOK + tokin0 +
                         tq * 4] = o;
        }
    } else {
        const float g = (EPI == 2) ? gamma[0] : 0.f;
        for (int e = t; e < 128 * (TN / 4); e += 256) {
            int r = e / (TN / 4), c4 = e % (TN / 4);
            float4 o = *(float4*)&Cs[r * LDCS + c4 * 4];
            size_t base =
                bz * sC + (size_t)(by * 128 + r) * ldC + bx * TN + c4 * 4;
            if (EPI == 2) {
                float4 xr = *(const float4*)&xres[base];
                o.x = g * o.x + xr.x;
                o.y = g * o.y + xr.y;
                o.z = g * o.z + xr.z;
                o.w = g * o.w + xr.w;
            }
            *(float4*)&C[base] = o;
        }
    }
}

// ---------------- row softmax (writes tf32-rounded probs) --------------------
__global__ __launch_bounds__(256) void softmax_kernel(float* __restrict__ S) {
    __shared__ float red[8];
    const size_t row = blockIdx.x;
    float4* p = (float4*)(S + row * NTOK);
    const int t = threadIdx.x, w = t >> 5, lane = t & 31;

    float4 v[4];
#pragma unroll
    for (int j = 0; j < 4; j++) v[j] = p[t + j * 256];

    float mx = -3.4e38f;
#pragma unroll
    for (int j = 0; j < 4; j++)
        mx = fmaxf(mx, fmaxf(fmaxf(v[j].x, v[j].y), fmaxf(v[j].z, v[j].w)));
#pragma unroll
    for (int o = 16; o; o >>= 1) mx = fmaxf(mx, __shfl_xor_sync(~0u, mx, o));
    if (lane == 0) red[w] = mx;
    __syncthreads();
    mx = red[0];
#pragma unroll
    for (int i = 1; i < 8; i++) mx = fmaxf(mx, red[i]);
    __syncthreads();

    float sum = 0.f;
#pragma unroll
    for (int j = 0; j < 4; j++) {
        v[j].x = __expf(v[j].x - mx);
        v[j].y = __expf(v[j].y - mx);
        v[j].z = __expf(v[j].z - mx);
        v[j].w = __expf(v[j].w - mx);
        sum += v[j].x + v[j].y + v[j].z + v[j].w;
    }
#pragma unroll
    for (int o = 16; o; o >>= 1) sum += __shfl_xor_sync(~0u, sum, o);
    if (lane == 0) red[w] = sum;
    __syncthreads();
    sum = red[0];
#pragma unroll
    for (int i = 1; i < 8; i++) sum += red[i];
    float inv = 1.f / sum;
#pragma unroll
    for (int j = 0; j < 4; j++) {
        v[j].x = f2tf(v[j].x * inv);
        v[j].y = f2tf(v[j].y * inv);
        v[j].z = f2tf(v[j].z * inv);
        v[j].w = f2tf(v[j].w * inv);
        p[t + j * 256] = v[j];
    }
}

// ---------------------------------------------------------------------------
static inline int smem_async(int TN, bool split) {
    int stage = (split ? 2 : 1) * (128 + TN) * 36 * 4;
    int buf = 2 * stage;
    int cs = 128 * (TN + 4) * 4;
    return buf > cs ? buf : cs;
}

extern "C" void kernel_launch(void* const* d_in, const int* in_sizes, int n_in,
                              void* d_out, int out_size) {
    const float* x = (const float*)d_in[0];
    const float* Wb = (const float*)d_in[1];
    const float* Wc = (const float*)d_in[2];
    const float* Wd = (const float*)d_in[3];
    const float* gamma = (const float*)d_in[4];
    float* out = (float*)d_out;

    float *qkH, *qkL, *xrp, *vTp, *Sp, *WqkT, *WdT;
    cudaGetSymbolAddress((void**)&qkH, g_qkH);
    cudaGetSymbolAddress((void**)&qkL, g_qkL);
    cudaGetSymbolAddress((void**)&xrp, g_xr);
    cudaGetSymbolAddress((void**)&vTp, g_vT);
    cudaGetSymbolAddress((void**)&Sp, g_S);
    cudaGetSymbolAddress((void**)&WqkT, g_WqkT);
    cudaGetSymbolAddress((void**)&WdT, g_WdT);

    const int smem_qk = 2 * 2 * (128 + 128) * 36 * 4;
    cudaFuncSetAttribute(gemm_qk, cudaFuncAttributeMaxDynamicSharedMemorySize,
                         smem_qk);
    cudaFuncSetAttribute(gemm_async<128, 0, true>,
                         cudaFuncAttributeMaxDynamicSharedMemorySize,
                         smem_async(128, true));
    cudaFuncSetAttribute(gemm_async<256, 1, false>,
                         cudaFuncAttributeMaxDynamicSharedMemorySize,
                         smem_async(256, false));
    cudaFuncSetAttribute(gemm_async<256, 2, false>,
                         cudaFuncAttributeMaxDynamicSharedMemorySize,
                         smem_async(256, false));

    // producers
    round_x<<<(BNTOT * CC / 4 + 255) / 256, 256>>>((const float4*)x,
                                                   (float4*)xrp,
                                                   BNTOT * CC / 4);
    transpose_wqk<<<(128 * CC + 255) / 256, 256>>>(Wb, Wc, WqkT);
    transpose_w_round<<<(CC * CC + 255) / 256, 256>>>(Wd, WdT, CC, CC);

    // qk = X @ [Wb|Wc], split hi/lo outputs (M=16384, N=128, K=512)
    gemm_qk<<<dim3(1, BNTOT / 128), 256, smem_qk>>>(x, WqkT, qkH, qkL);
    // vT: v = X @ Wd transposed+rounded store (plain async)
    gemm_async<256, 1, false><<<dim3(CC / 256, BNTOT / 128, 1), 256,
                                smem_async(256, false)>>>(
        xrp, nullptr, WdT, nullptr, vTp, CC, CC, CC, 0, 0, 0, 0, nullptr,
        nullptr);
    // S = q k^T per batch (async split; K=64)
    gemm_async<128, 0, true><<<dim3(NTOK / 128, NTOK / 128, B_), 256,
                               smem_async(128, true)>>>(
        qkH, qkL, qkH + CRD, qkL + CRD, Sp, CRD, 128, 128, NTOK,
        (size_t)NTOK * 128, (size_t)NTOK * 128, (size_t)NTOK * NTOK, nullptr,
        nullptr);
    // softmax rows (writes rounded P)
    softmax_kernel<<<B_ * NTOK, 256>>>(Sp);
    // out = gamma * (P @ v) + x (plain async; K=4096)
    gemm_async<256, 2, false><<<dim3(CC / 256, NTOK / 128, B_), 256,
                                smem_async(256, false)>>>(
        Sp, nullptr, vTp, nullptr, out, NTOK, NTOK, NTOK, CC,
        (size_t)NTOK * NTOK, (size_t)CC * NTOK, (size_t)NTOK * CC, x, gamma);
}